// round 9
// baseline (speedup 1.0000x reference)
#include <cuda_runtime.h>

#define FULL 0xffffffffu

// ---------------------------------------------------------------------------
// Half-warp (16 lanes) per item, 2 items/warp.
// Full 8-qubit state: 256 amps = 16 lanes x 16 local amps.
// Slot (lg, j): wire w<4 -> bit w of j (local), wire w>=4 -> bit (w-4) of lg.
// Product phase: psi_q, psi_k, value as three interleaved 16-amp states.
// Cross phase: branchless gates; CNOT(i,4+i)x4 as ONE dynamic shuffle;
// CNOT(4+i,i)x4 free via basis relabel; final rot + measurement folded into
// conjugated observables. Reductions are segmented butterflies: 8 values over
// 16 lanes in 4 shuffle stages; transcendentals computed once per value and
// broadcast.
// ---------------------------------------------------------------------------

__device__ __forceinline__ float2 shfl2x(float2 v, int m) {
    v.x = __shfl_xor_sync(FULL, v.x, m);
    v.y = __shfl_xor_sync(FULL, v.y, m);
    return v;
}
__device__ __forceinline__ float2 shfl2i(float2 v, int src) {  // within 16-group
    v.x = __shfl_sync(FULL, v.x, src, 16);
    v.y = __shfl_sync(FULL, v.y, src, 16);
    return v;
}
__device__ __forceinline__ float2 shfl2a(float2 v, int src) {  // absolute lane
    v.x = __shfl_sync(FULL, v.x, src);
    v.y = __shfl_sync(FULL, v.y, src);
    return v;
}

// Segmented butterfly: reduce 8 per-lane values over the 16-lane group.
// Result: lane with bits (b3,b2,b1) holds sum of v[t] with t = 4*b3 + 2*b2 + b1
// (duplicated over bit0).
__device__ __forceinline__ float segred8(const float* v, int lg) {
    const bool b3 = lg & 8, b2 = lg & 4, b1 = lg & 2;
    float s0 = b3 ? v[0] : v[4];
    float s1 = b3 ? v[1] : v[5];
    float s2 = b3 ? v[2] : v[6];
    float s3 = b3 ? v[3] : v[7];
    s0 = __shfl_xor_sync(FULL, s0, 8);
    s1 = __shfl_xor_sync(FULL, s1, 8);
    s2 = __shfl_xor_sync(FULL, s2, 8);
    s3 = __shfl_xor_sync(FULL, s3, 8);
    float n0 = (b3 ? v[4] : v[0]) + s0;
    float n1 = (b3 ? v[5] : v[1]) + s1;
    float n2 = (b3 ? v[6] : v[2]) + s2;
    float n3 = (b3 ? v[7] : v[3]) + s3;
    float t0 = b2 ? n0 : n2;
    float t1 = b2 ? n1 : n3;
    t0 = __shfl_xor_sync(FULL, t0, 4);
    t1 = __shfl_xor_sync(FULL, t1, 4);
    n0 = (b2 ? n2 : n0) + t0;
    n1 = (b2 ? n3 : n1) + t1;
    float u0 = b1 ? n0 : n1;
    u0 = __shfl_xor_sync(FULL, u0, 2);
    n0 = (b1 ? n1 : n0) + u0;
    n0 += __shfl_xor_sync(FULL, n0, 1);
    return n0;
}

// a_new = c*a + (-i s)*o
__device__ __forceinline__ float2 rxmix(float2 a, float2 o, float c, float s) {
    return make_float2(c * a.x + s * o.y, c * a.y - s * o.x);
}

// general unitary [[u00,u01],[-conj(u01),conj(u00)]], own bit b
__device__ __forceinline__ float2 genmix(float2 x, float2 t, float4 u, int b) {
    float cx = u.x, cy = b ? -u.y : u.y;
    float dx = b ? -u.z : u.z, dy = u.w;
    return make_float2(cx * x.x - cy * x.y + dx * t.x - dy * t.y,
                       cx * x.y + cy * x.x + dx * t.y + dy * t.x);
}

__device__ __forceinline__ float4 fuse_rx(float4 g, float c, float s) {
    float2 g00 = make_float2(g.x, g.y), g01 = make_float2(g.z, g.w);
    float2 u00 = rxmix(g00, g01, c, s);
    float2 u01 = rxmix(g01, g00, c, s);
    return make_float4(u00.x, u00.y, u01.x, u01.y);
}

// ---------------------------------------------------------------------------

__global__ void __launch_bounds__(64, 7)
qa_fused(const float* __restrict__ x_text, const float* __restrict__ x_image,
         const float* __restrict__ W_text, const float* __restrict__ b_text,
         const float* __restrict__ W_image, const float* __restrict__ b_image,
         const float* __restrict__ qr, const float* __restrict__ qc,
         const float* __restrict__ kr, const float* __restrict__ kc,
         const float* __restrict__ vr, const float* __restrict__ vc,
         const float* __restrict__ cr, const float* __restrict__ cc,
         const float* __restrict__ cc2, const float* __restrict__ gates,
         float* __restrict__ out, int B, int IN) {
    // sf: [0..3] q L1, [4..7] q L2, [8..11] k L1, [12..15] k L2,
    //     [16..19] unused, [20..23] v L1, [24..27] v L2
    __shared__ float4 sf[28];
    // scs: [0..7] q_crx, [8..15] k_crx, [16..23] c_crx, [24..31] c_crx2, [32..39] v_crx
    __shared__ float2 scs[40];
    __shared__ float sgates[4];
    __shared__ float4 szm[4];  // (p, m.x, m.y, r)
    __shared__ float2 sn[4];   // (n.x, n.y)

    for (int t = threadIdx.x; t < 76; t += blockDim.x) {
        if (t < 28) {
            int grp = t >> 2, i = t & 3;
            float a = 0.f, b = 0.f, c = 0.f;
            switch (grp) {
                case 0: a = qr[3 * i];      b = qr[3 * i + 1];      c = qr[3 * i + 2];      break;
                case 1: a = qr[12 + 3 * i]; b = qr[12 + 3 * i + 1]; c = qr[12 + 3 * i + 2]; break;
                case 2: a = kr[3 * i];      b = kr[3 * i + 1];      c = kr[3 * i + 2];      break;
                case 3: a = kr[12 + 3 * i]; b = kr[12 + 3 * i + 1]; c = kr[12 + 3 * i + 2]; break;
                case 4: a = cr[3 * i];      b = cr[3 * i + 1];      c = cr[3 * i + 2];      break;
                case 5: a = vr[3 * i];      b = vr[3 * i + 1];      c = vr[3 * i + 2];      break;
                case 6: a = vr[12 + 3 * i]; b = vr[12 + 3 * i + 1]; c = vr[12 + 3 * i + 2]; break;
            }
            float cb = cosf(0.5f * b), sb = sinf(0.5f * b);
            float sum = 0.5f * (a + c), dif = 0.5f * (a - c);
            sf[t] = make_float4(cb * cosf(sum), -cb * sinf(sum),
                                sb * sinf(dif), -sb * cosf(dif));
        } else if (t < 68) {
            int u = t - 28;
            float p;
            if (u < 8) p = qc[u];
            else if (u < 16) p = kc[u - 8];
            else if (u < 24) p = cc[u - 16];
            else if (u < 32) p = cc2[u - 24];
            else p = vc[u - 32];
            float s, c;
            sincosf(0.5f * p, &s, &c);
            scs[u] = make_float2(c, s);
        } else if (t < 72) {
            sgates[t - 68] = gates[t - 68];
        } else {
            int i = t - 72;
            float aa = cr[3 * i], b = cr[3 * i + 1], c = cr[3 * i + 2];
            float cb = cosf(0.5f * b), sb = sinf(0.5f * b);
            float sum = 0.5f * (aa + c), dif = 0.5f * (aa - c);
            float alx = cb * cosf(sum), aly = -cb * sinf(sum);
            float bex = sb * sinf(dif), bey = -sb * cosf(dif);
            float p = alx * alx + aly * aly - bex * bex - bey * bey;
            float mx = 2.f * (alx * bex + aly * bey);
            float my = 2.f * (alx * bey - aly * bex);
            float r = -2.f * (alx * bex - aly * bey);
            float nx = (alx * alx - aly * aly) - (bex * bex - bey * bey);
            float ny = -2.f * alx * aly - 2.f * bex * bey;
            szm[i] = make_float4(p, mx, my, r);
            sn[i] = make_float2(nx, ny);
        }
    }
    __syncthreads();

    const int lane = threadIdx.x & 31;
    const int half = lane >> 4;
    const int lg = lane & 15;
    const int gbase = lane & 16;
    const int wsel = ((lg >> 2) & 1) * 2 + ((lg >> 1) & 1);  // this lane's value index
    const int gw = (int)((blockIdx.x * blockDim.x + threadIdx.x) >> 5);
    const int item = gw * 2 + half;
    const int itc = item < B ? item : (B - 1);

    // ---- projections: segmented reduce + single sincos per value + broadcast ----
    float cqv[4], sqv[4], ckv[4], skv[4];
    {
        const float2* xt2 = (const float2*)(x_text + (long)itc * IN);
        const float2* xi2 = (const float2*)(x_image + (long)itc * IN);
        const int hin = IN >> 1;
        float pv[8] = {0.f, 0.f, 0.f, 0.f, 0.f, 0.f, 0.f, 0.f};
        for (int k = lg; k < hin; k += 16) {
            float2 xa = __ldg(&xt2[k]);
            float2 xb = __ldg(&xi2[k]);
#pragma unroll
            for (int r = 0; r < 4; r++) {
                float2 wa = __ldg((const float2*)(W_text + r * IN) + k);
                float2 wb = __ldg((const float2*)(W_image + r * IN) + k);
                pv[r] += xa.x * wa.x + xa.y * wa.y;
                pv[4 + r] += xb.x * wb.x + xb.y * wb.y;
            }
        }
        float xval = segred8(pv, lg);   // lane: g=b3 (0:q,1:k), w=wsel
        const bool gk = lg & 8;
        xval += __ldg((gk ? b_image : b_text) + wsel);
        float s_ang, c_ang;
        __sincosf(0.5f * xval, &s_ang, &c_ang);
#pragma unroll
        for (int i = 0; i < 4; i++) {
            cqv[i] = __shfl_sync(FULL, c_ang, gbase | (2 * i));
            sqv[i] = __shfl_sync(FULL, s_ang, gbase | (2 * i));
            ckv[i] = __shfl_sync(FULL, c_ang, gbase | 8 | (2 * i));
            skv[i] = __shfl_sync(FULL, s_ang, gbase | 8 | (2 * i));
        }
    }

    // ---- product phase: three interleaved 16-amp rings (branchless) ----
    float2 vq = make_float2(lg == 0 ? 1.f : 0.f, 0.f);
    float2 vk = vq, vv = vq;

#pragma unroll
    for (int i = 0; i < 4; i++) {  // L1 with fused data RX
        float4 uq = fuse_rx(sf[i], cqv[i], sqv[i]);
        float4 uk = fuse_rx(sf[8 + i], ckv[i], skv[i]);
        float4 uv = fuse_rx(sf[20 + i], ckv[i], skv[i]);
        const int b = (lg >> i) & 1;
        float2 tq = shfl2x(vq, 1 << i);
        float2 tk = shfl2x(vk, 1 << i);
        float2 tv = shfl2x(vv, 1 << i);
        vq = genmix(vq, tq, uq, b);
        vk = genmix(vk, tk, uk, b);
        vv = genmix(vv, tv, uv, b);
    }
#pragma unroll
    for (int i = 0; i < 4; i++) {  // CRX rings (branchless select)
        const int m = 1 << ((i + 1) & 3);
        const bool p = (lg >> i) & 1;
        float cq = p ? scs[i].x : 1.f,      sq = p ? scs[i].y : 0.f;
        float ck = p ? scs[8 + i].x : 1.f,  sk = p ? scs[8 + i].y : 0.f;
        float cv = p ? scs[32 + i].x : 1.f, sv = p ? scs[32 + i].y : 0.f;
        float2 tq = shfl2x(vq, m), tk = shfl2x(vk, m), tv = shfl2x(vv, m);
        vq = rxmix(vq, tq, cq, sq);
        vk = rxmix(vk, tk, ck, sk);
        vv = rxmix(vv, tv, cv, sv);
    }
#pragma unroll
    for (int i = 0; i < 4; i++) {  // IsingXX rings
        const int m = (1 << i) | (1 << ((i + 1) & 3));
        float2 tq = shfl2x(vq, m), tk = shfl2x(vk, m), tv = shfl2x(vv, m);
        vq = rxmix(vq, tq, scs[4 + i].x, scs[4 + i].y);
        vk = rxmix(vk, tk, scs[12 + i].x, scs[12 + i].y);
        vv = rxmix(vv, tv, scs[36 + i].x, scs[36 + i].y);
    }
#pragma unroll
    for (int i = 0; i < 4; i++) {  // L2
        const int b = (lg >> i) & 1;
        float2 tq = shfl2x(vq, 1 << i);
        float2 tk = shfl2x(vk, 1 << i);
        float2 tv = shfl2x(vv, 1 << i);
        vq = genmix(vq, tq, sf[4 + i], b);
        vk = genmix(vk, tk, sf[12 + i], b);
        vv = genmix(vv, tv, sf[24 + i], b);
    }

    // ---- assemble full state: a[j] = psi_q[j] * psi_k[lg] ----
    float2 a[16];
#pragma unroll
    for (int j = 0; j < 16; j++) {
        float2 qj = shfl2i(vq, j);
        a[j] = make_float2(qj.x * vk.x - qj.y * vk.y,
                           qj.x * vk.y + qj.y * vk.x);
    }

    // ---- cross entanglers (branchless) ----
#pragma unroll
    for (int i = 0; i < 4; i++) {  // CRX(i,4+i): local ctrl -> lane target
        const float c = scs[16 + i].x, s = scs[16 + i].y;
        const int ml = 1 << i;
#pragma unroll
        for (int j = 0; j < 16; j++)
            if ((j >> i) & 1) {
                float2 t = shfl2x(a[j], ml);
                a[j] = rxmix(a[j], t, c, s);
            }
    }
#pragma unroll
    for (int i = 0; i < 4; i++) {  // CRX(4+i,i): lane ctrl -> local target
        const bool e = (lg >> i) & 1;
        const float c = e ? scs[20 + i].x : 1.f, s = e ? scs[20 + i].y : 0.f;
        const int m = 1 << i;
#pragma unroll
        for (int j = 0; j < 16; j++)
            if (!(j & m)) {
                int j2 = j | m;
                float2 x = a[j], p = a[j2];
                a[j] = rxmix(x, p, c, s);
                a[j2] = rxmix(p, x, c, s);
            }
    }
#pragma unroll
    for (int i = 0; i < 4; i++) {  // CRX2(i, ((i+1)&3)+4)
        const float c = scs[24 + i].x, s = scs[24 + i].y;
        const int ml = 1 << ((i + 1) & 3);
#pragma unroll
        for (int j = 0; j < 16; j++)
            if ((j >> i) & 1) {
                float2 t = shfl2x(a[j], ml);
                a[j] = rxmix(a[j], t, c, s);
            }
    }
#pragma unroll
    for (int i = 0; i < 4; i++) {  // CRX2(4+i, (i+1)&3)
        const bool e = (lg >> i) & 1;
        const float c = e ? scs[28 + i].x : 1.f, s = e ? scs[28 + i].y : 0.f;
        const int m = 1 << ((i + 1) & 3);
#pragma unroll
        for (int j = 0; j < 16; j++)
            if (!(j & m)) {
                int j2 = j | m;
                float2 x = a[j], p = a[j2];
                a[j] = rxmix(x, p, c, s);
                a[j2] = rxmix(p, x, c, s);
            }
    }
    // all 4 CNOT(i,4+i): one dynamic-src shuffle stage
#pragma unroll
    for (int j = 0; j < 16; j++) {
        int src = gbase | (lg ^ j);
        a[j] = shfl2a(a[j], src);
    }
    // all 4 CNOT(4+i,i): FREE via basis relabel (slot j holds basis j^lg).

    // ---- measurement with folded final rot: norms once, sgn folded per-w ----
    float cc0[4], ss0[4];
    {
        float nj[16];
#pragma unroll
        for (int j = 0; j < 16; j++) nj[j] = a[j].x * a[j].x + a[j].y * a[j].y;

        float acc[8];
#pragma unroll
        for (int w = 0; w < 4; w++) {
            const int m = 1 << w;
            const float4 zm = szm[w];
            const float2 nn = sn[w];
            const float sgn = ((lg >> w) & 1) ? -1.f : 1.f;
            const float zmD = zm.x * sgn, zmR = 2.f * zm.y, zmI = 2.f * zm.z * sgn;
            const float xmD = zm.w * sgn, xmR = 2.f * nn.x, xmI = 2.f * nn.y * sgn;
            float z = 0.f, x = 0.f;
#pragma unroll
            for (int j = 0; j < 16; j++) {
                if (j & m) continue;
                float2 e0 = a[j], e1 = a[j | m];
                float D = nj[j] - nj[j | m];
                float R = e0.x * e1.x + e0.y * e1.y;
                float I = e0.x * e1.y - e0.y * e1.x;
                z += zmD * D + zmR * R - zmI * I;
                x += xmD * D + xmR * R - xmI * I;
            }
            acc[w] = z;
            acc[4 + w] = x;
        }
        float S = segred8(acc, lg);               // lane: g=b3 (0:z,1:x), w=wsel
        float other = __shfl_xor_sync(FULL, S, 8);
        float amp = sqrtf(S * S + other * other);
        float ang = tanhf(amp) * sgates[wsel];
        float ss_l, cc_l;
        __sincosf(0.5f * ang, &ss_l, &cc_l);
#pragma unroll
        for (int i = 0; i < 4; i++) {
            cc0[i] = __shfl_sync(FULL, cc_l, gbase | (2 * i));
            ss0[i] = __shfl_sync(FULL, ss_l, gbase | (2 * i));
        }
    }

    // ---- value tail: amp-RX fused pairwise ----
    {
        {   // wires 0,1 (masks 1,2)
            float AB = cc0[0] * cc0[1], AsB = cc0[0] * ss0[1],
                  sAB = ss0[0] * cc0[1], ss = ss0[0] * ss0[1];
            float2 t0 = shfl2x(vv, 1), t1 = shfl2x(vv, 2), t2 = shfl2x(vv, 3);
            vv = make_float2(AB * vv.x + sAB * t0.y + AsB * t1.y - ss * t2.x,
                             AB * vv.y - sAB * t0.x - AsB * t1.x - ss * t2.y);
        }
        {   // wires 2,3 (masks 4,8)
            float AB = cc0[2] * cc0[3], AsB = cc0[2] * ss0[3],
                  sAB = ss0[2] * cc0[3], ss = ss0[2] * ss0[3];
            float2 t0 = shfl2x(vv, 4), t1 = shfl2x(vv, 8), t2 = shfl2x(vv, 12);
            vv = make_float2(AB * vv.x + sAB * t0.y + AsB * t1.y - ss * t2.x,
                             AB * vv.y - sAB * t0.x - AsB * t1.x - ss * t2.y);
        }
    }
    // CNOT ring folded into measurement via basis permutation pi
    int pi = lg;
    pi ^= (pi & 1) << 1;
    pi ^= ((pi >> 1) & 1) << 2;
    pi ^= ((pi >> 2) & 1) << 3;
    pi ^= (pi >> 3) & 1;

    // ---- final measurement: segmented reduce + direct scatter store ----
    {
        float ov[8];
        const float nv = vv.x * vv.x + vv.y * vv.y;
#pragma unroll
        for (int w = 0; w < 4; w++) ov[w] = ((pi >> w) & 1) ? -nv : nv;
#pragma unroll
        for (int w = 0; w < 4; w++) {
            int r = pi ^ (1 << w);
            r ^= (r >> 3) & 1;
            r ^= ((r >> 2) & 1) << 3;
            r ^= ((r >> 1) & 1) << 2;
            r ^= (r & 1) << 1;
            float2 t = shfl2a(vv, gbase | r);
            ov[4 + w] = vv.x * t.x + vv.y * t.y;
        }
        float oS = segred8(ov, lg);  // lane: out index = 4*b3 + wsel
        const int oidx = ((lg >> 3) & 1) * 4 + wsel;
        if (!(lg & 1) && item < B)
            out[(long)item * 8 + oidx] = oS;
    }
}

// ---------------------------------------------------------------------------

extern "C" void kernel_launch(void* const* d_in, const int* in_sizes, int n_in,
                              void* d_out, int out_size) {
    const float* x_text  = (const float*)d_in[0];
    const float* x_image = (const float*)d_in[1];
    const float* W_text  = (const float*)d_in[2];
    const float* b_text  = (const float*)d_in[3];
    const float* W_image = (const float*)d_in[4];
    const float* b_image = (const float*)d_in[5];
    const float* q_rot   = (const float*)d_in[6];
    const float* q_crx   = (const float*)d_in[7];
    const float* k_rot   = (const float*)d_in[8];
    const float* k_crx   = (const float*)d_in[9];
    const float* v_rot   = (const float*)d_in[10];
    const float* v_crx   = (const float*)d_in[11];
    const float* c_rot   = (const float*)d_in[12];
    const float* c_crx   = (const float*)d_in[13];
    const float* c_crx2  = (const float*)d_in[14];
    const float* gates   = (const float*)d_in[15];

    int IN = in_sizes[2] / 4;   // W_text is [4, IN]
    int B  = in_sizes[0] / IN;  // x_text is [B, IN]

    int nwarps = (B + 1) / 2;   // 2 items per warp
    int threads = 64;
    int blocks = (nwarps * 32 + threads - 1) / threads;
    qa_fused<<<blocks, threads>>>(x_text, x_image, W_text, b_text, W_image, b_image,
                                  q_rot, q_crx, k_rot, k_crx, v_rot, v_crx,
                                  c_rot, c_crx, c_crx2, gates,
                                  (float*)d_out, B, IN);
}

// round 10
// speedup vs baseline: 1.0194x; 1.0194x over previous
#include <cuda_runtime.h>

#define FULL 0xffffffffu
typedef unsigned long long u64;

// ---------------------------------------------------------------------------
// Half-warp (16 lanes) per item, 2 items/warp.
// Full 8-qubit state: 256 amps = 16 lanes x 16 local amps.
// Slot (lg, j): wire w<4 -> bit w of j (local), wire w>=4 -> bit (w-4) of lg.
// Cross phase uses the PHASE-TWISTED representation b_j = (-i)^pop(j) * a_j:
// local-axis RX mixings become REAL rotations -> packed f32x2 FMA.
// Lane-axis gates keep sigma invariant (same j on both sides) -> unchanged.
// Measurement: P_a = i * P_b  =>  (R,I) -> (-I_b, R_b), folded into coeffs.
// ---------------------------------------------------------------------------

__device__ __forceinline__ u64 pk(float a, float b) {
    u64 r;
    asm("mov.b64 %0, {%1, %2};" : "=l"(r) : "f"(a), "f"(b));
    return r;
}
__device__ __forceinline__ float2 upk(u64 v) {
    float2 r;
    asm("mov.b64 {%0, %1}, %2;" : "=f"(r.x), "=f"(r.y) : "l"(v));
    return r;
}
__device__ __forceinline__ u64 f2mul(u64 a, u64 b) {
    u64 r;
    asm("mul.rn.f32x2 %0, %1, %2;" : "=l"(r) : "l"(a), "l"(b));
    return r;
}
__device__ __forceinline__ u64 f2fma(u64 a, u64 b, u64 c) {
    u64 r;
    asm("fma.rn.f32x2 %0, %1, %2, %3;" : "=l"(r) : "l"(a), "l"(b), "l"(c));
    return r;
}

__device__ __forceinline__ float2 shfl2x(float2 v, int m) {
    v.x = __shfl_xor_sync(FULL, v.x, m);
    v.y = __shfl_xor_sync(FULL, v.y, m);
    return v;
}

// Segmented butterfly: reduce 8 per-lane values over the 16-lane group.
// Result: lane with bits (b3,b2,b1) holds sum of v[4*b3+2*b2+b1] (dup over bit0).
__device__ __forceinline__ float segred8(const float* v, int lg) {
    const bool b3 = lg & 8, b2 = lg & 4, b1 = lg & 2;
    float s0 = b3 ? v[0] : v[4];
    float s1 = b3 ? v[1] : v[5];
    float s2 = b3 ? v[2] : v[6];
    float s3 = b3 ? v[3] : v[7];
    s0 = __shfl_xor_sync(FULL, s0, 8);
    s1 = __shfl_xor_sync(FULL, s1, 8);
    s2 = __shfl_xor_sync(FULL, s2, 8);
    s3 = __shfl_xor_sync(FULL, s3, 8);
    float n0 = (b3 ? v[4] : v[0]) + s0;
    float n1 = (b3 ? v[5] : v[1]) + s1;
    float n2 = (b3 ? v[6] : v[2]) + s2;
    float n3 = (b3 ? v[7] : v[3]) + s3;
    float t0 = b2 ? n0 : n2;
    float t1 = b2 ? n1 : n3;
    t0 = __shfl_xor_sync(FULL, t0, 4);
    t1 = __shfl_xor_sync(FULL, t1, 4);
    n0 = (b2 ? n2 : n0) + t0;
    n1 = (b2 ? n3 : n1) + t1;
    float u0 = b1 ? n0 : n1;
    u0 = __shfl_xor_sync(FULL, u0, 2);
    n0 = (b1 ? n1 : n0) + u0;
    n0 += __shfl_xor_sync(FULL, n0, 1);
    return n0;
}

// a_new = c*a + (-i s)*o
__device__ __forceinline__ float2 rxmix(float2 a, float2 o, float c, float s) {
    return make_float2(c * a.x + s * o.y, c * a.y - s * o.x);
}

// general unitary [[u00,u01],[-conj(u01),conj(u00)]], own bit b
__device__ __forceinline__ float2 genmix(float2 x, float2 t, float4 u, int b) {
    float cx = u.x, cy = b ? -u.y : u.y;
    float dx = b ? -u.z : u.z, dy = u.w;
    return make_float2(cx * x.x - cy * x.y + dx * t.x - dy * t.y,
                       cx * x.y + cy * x.x + dx * t.y + dy * t.x);
}

__device__ __forceinline__ float4 fuse_rx(float4 g, float c, float s) {
    float2 g00 = make_float2(g.x, g.y), g01 = make_float2(g.z, g.w);
    float2 u00 = rxmix(g00, g01, c, s);
    float2 u01 = rxmix(g01, g00, c, s);
    return make_float4(u00.x, u00.y, u01.x, u01.y);
}

// ---------------------------------------------------------------------------

__global__ void __launch_bounds__(64, 7)
qa_fused(const float* __restrict__ x_text, const float* __restrict__ x_image,
         const float* __restrict__ W_text, const float* __restrict__ b_text,
         const float* __restrict__ W_image, const float* __restrict__ b_image,
         const float* __restrict__ qr, const float* __restrict__ qc,
         const float* __restrict__ kr, const float* __restrict__ kc,
         const float* __restrict__ vr, const float* __restrict__ vc,
         const float* __restrict__ cr, const float* __restrict__ cc,
         const float* __restrict__ cc2, const float* __restrict__ gates,
         float* __restrict__ out, int B, int IN) {
    __shared__ float4 sf[28];
    __shared__ float2 scs[40];
    __shared__ float sgates[4];
    __shared__ float4 szm[4];  // (p, m.x, m.y, r)
    __shared__ float2 sn[4];   // (n.x, n.y)

    for (int t = threadIdx.x; t < 76; t += blockDim.x) {
        if (t < 28) {
            int grp = t >> 2, i = t & 3;
            float a = 0.f, b = 0.f, c = 0.f;
            switch (grp) {
                case 0: a = qr[3 * i];      b = qr[3 * i + 1];      c = qr[3 * i + 2];      break;
                case 1: a = qr[12 + 3 * i]; b = qr[12 + 3 * i + 1]; c = qr[12 + 3 * i + 2]; break;
                case 2: a = kr[3 * i];      b = kr[3 * i + 1];      c = kr[3 * i + 2];      break;
                case 3: a = kr[12 + 3 * i]; b = kr[12 + 3 * i + 1]; c = kr[12 + 3 * i + 2]; break;
                case 4: a = cr[3 * i];      b = cr[3 * i + 1];      c = cr[3 * i + 2];      break;
                case 5: a = vr[3 * i];      b = vr[3 * i + 1];      c = vr[3 * i + 2];      break;
                case 6: a = vr[12 + 3 * i]; b = vr[12 + 3 * i + 1]; c = vr[12 + 3 * i + 2]; break;
            }
            float cb = cosf(0.5f * b), sb = sinf(0.5f * b);
            float sum = 0.5f * (a + c), dif = 0.5f * (a - c);
            sf[t] = make_float4(cb * cosf(sum), -cb * sinf(sum),
                                sb * sinf(dif), -sb * cosf(dif));
        } else if (t < 68) {
            int u = t - 28;
            float p;
            if (u < 8) p = qc[u];
            else if (u < 16) p = kc[u - 8];
            else if (u < 24) p = cc[u - 16];
            else if (u < 32) p = cc2[u - 24];
            else p = vc[u - 32];
            float s, c;
            sincosf(0.5f * p, &s, &c);
            scs[u] = make_float2(c, s);
        } else if (t < 72) {
            sgates[t - 68] = gates[t - 68];
        } else {
            int i = t - 72;
            float aa = cr[3 * i], b = cr[3 * i + 1], c = cr[3 * i + 2];
            float cb = cosf(0.5f * b), sb = sinf(0.5f * b);
            float sum = 0.5f * (aa + c), dif = 0.5f * (aa - c);
            float alx = cb * cosf(sum), aly = -cb * sinf(sum);
            float bex = sb * sinf(dif), bey = -sb * cosf(dif);
            float p = alx * alx + aly * aly - bex * bex - bey * bey;
            float mx = 2.f * (alx * bex + aly * bey);
            float my = 2.f * (alx * bey - aly * bex);
            float r = -2.f * (alx * bex - aly * bey);
            float nx = (alx * alx - aly * aly) - (bex * bex - bey * bey);
            float ny = -2.f * alx * aly - 2.f * bex * bey;
            szm[i] = make_float4(p, mx, my, r);
            sn[i] = make_float2(nx, ny);
        }
    }
    __syncthreads();

    const int lane = threadIdx.x & 31;
    const int half = lane >> 4;
    const int lg = lane & 15;
    const int gbase = lane & 16;
    const int wsel = ((lg >> 2) & 1) * 2 + ((lg >> 1) & 1);
    const int gw = (int)((blockIdx.x * blockDim.x + threadIdx.x) >> 5);
    const int item = gw * 2 + half;
    const int itc = item < B ? item : (B - 1);

    // ---- projections: segmented reduce + single sincos per value + broadcast ----
    float cqv[4], sqv[4], ckv[4], skv[4];
    {
        const float2* xt2 = (const float2*)(x_text + (long)itc * IN);
        const float2* xi2 = (const float2*)(x_image + (long)itc * IN);
        const int hin = IN >> 1;
        float pv[8] = {0.f, 0.f, 0.f, 0.f, 0.f, 0.f, 0.f, 0.f};
        for (int k = lg; k < hin; k += 16) {
            float2 xa = __ldg(&xt2[k]);
            float2 xb = __ldg(&xi2[k]);
#pragma unroll
            for (int r = 0; r < 4; r++) {
                float2 wa = __ldg((const float2*)(W_text + r * IN) + k);
                float2 wb = __ldg((const float2*)(W_image + r * IN) + k);
                pv[r] += xa.x * wa.x + xa.y * wa.y;
                pv[4 + r] += xb.x * wb.x + xb.y * wb.y;
            }
        }
        float xval = segred8(pv, lg);
        const bool gk = lg & 8;
        xval += __ldg((gk ? b_image : b_text) + wsel);
        float s_ang, c_ang;
        __sincosf(0.5f * xval, &s_ang, &c_ang);
#pragma unroll
        for (int i = 0; i < 4; i++) {
            cqv[i] = __shfl_sync(FULL, c_ang, gbase | (2 * i));
            sqv[i] = __shfl_sync(FULL, s_ang, gbase | (2 * i));
            ckv[i] = __shfl_sync(FULL, c_ang, gbase | 8 | (2 * i));
            skv[i] = __shfl_sync(FULL, s_ang, gbase | 8 | (2 * i));
        }
    }

    // ---- product phase: three interleaved 16-amp rings (branchless) ----
    float2 vq = make_float2(lg == 0 ? 1.f : 0.f, 0.f);
    float2 vk = vq, vv = vq;

#pragma unroll
    for (int i = 0; i < 4; i++) {
        float4 uq = fuse_rx(sf[i], cqv[i], sqv[i]);
        float4 uk = fuse_rx(sf[8 + i], ckv[i], skv[i]);
        float4 uv = fuse_rx(sf[20 + i], ckv[i], skv[i]);
        const int b = (lg >> i) & 1;
        float2 tq = shfl2x(vq, 1 << i);
        float2 tk = shfl2x(vk, 1 << i);
        float2 tv = shfl2x(vv, 1 << i);
        vq = genmix(vq, tq, uq, b);
        vk = genmix(vk, tk, uk, b);
        vv = genmix(vv, tv, uv, b);
    }
#pragma unroll
    for (int i = 0; i < 4; i++) {
        const int m = 1 << ((i + 1) & 3);
        const bool p = (lg >> i) & 1;
        float cq = p ? scs[i].x : 1.f,      sq = p ? scs[i].y : 0.f;
        float ck = p ? scs[8 + i].x : 1.f,  sk = p ? scs[8 + i].y : 0.f;
        float cv = p ? scs[32 + i].x : 1.f, sv = p ? scs[32 + i].y : 0.f;
        float2 tq = shfl2x(vq, m), tk = shfl2x(vk, m), tv = shfl2x(vv, m);
        vq = rxmix(vq, tq, cq, sq);
        vk = rxmix(vk, tk, ck, sk);
        vv = rxmix(vv, tv, cv, sv);
    }
#pragma unroll
    for (int i = 0; i < 4; i++) {
        const int m = (1 << i) | (1 << ((i + 1) & 3));
        float2 tq = shfl2x(vq, m), tk = shfl2x(vk, m), tv = shfl2x(vv, m);
        vq = rxmix(vq, tq, scs[4 + i].x, scs[4 + i].y);
        vk = rxmix(vk, tk, scs[12 + i].x, scs[12 + i].y);
        vv = rxmix(vv, tv, scs[36 + i].x, scs[36 + i].y);
    }
#pragma unroll
    for (int i = 0; i < 4; i++) {
        const int b = (lg >> i) & 1;
        float2 tq = shfl2x(vq, 1 << i);
        float2 tk = shfl2x(vk, 1 << i);
        float2 tv = shfl2x(vv, 1 << i);
        vq = genmix(vq, tq, sf[4 + i], b);
        vk = genmix(vk, tk, sf[12 + i], b);
        vv = genmix(vv, tv, sf[24 + i], b);
    }

    // ---- assemble full state in b-rep: b[j] = sigma_j * psi_q[j] * psi_k[lg] ----
    // Fold sigma into vq before broadcast: vq2 = sigma_{lg} * vq,
    // sigma = (-i)^popcount(lg over 4 bits).
    u64 A[16];
    {
        int pop = __popc(lg);
        bool p1 = pop & 1, p2 = pop & 2;
        float tx = p1 ? vq.y : vq.x;
        float ty = p1 ? -vq.x : vq.y;
        float2 vq2 = make_float2(p2 ? -tx : tx, p2 ? -ty : ty);
#pragma unroll
        for (int j = 0; j < 16; j++) {
            float qx = __shfl_sync(FULL, vq2.x, j, 16);
            float qy = __shfl_sync(FULL, vq2.y, j, 16);
            A[j] = pk(qx * vk.x - qy * vk.y, qx * vk.y + qy * vk.x);
        }
    }

    // ---- cross entanglers in b-rep ----
    // CRX(i,4+i): local ctrl -> lane target. Partner has same j -> same sigma:
    // complex mix new = C2*b + (s,-s)*(t.y,t.x).
#pragma unroll
    for (int i = 0; i < 4; i++) {
        const float c = scs[16 + i].x, s = scs[16 + i].y;
        const u64 C2 = pk(c, c), S2 = pk(s, -s);
        const int ml = 1 << i;
#pragma unroll
        for (int j = 0; j < 16; j++)
            if ((j >> i) & 1) {
                float2 h = upk(A[j]);
                float tx = __shfl_xor_sync(FULL, h.x, ml);
                float ty = __shfl_xor_sync(FULL, h.y, ml);
                A[j] = f2fma(S2, pk(ty, tx), f2mul(C2, A[j]));
            }
    }
    // CRX(4+i,i): lane ctrl -> local target. In b-rep this is a REAL rotation:
    // new0 = c*b0 + s*b1 ; new1 = c*b1 - s*b0  (componentwise, packed).
#pragma unroll
    for (int i = 0; i < 4; i++) {
        const bool e = (lg >> i) & 1;
        const float c = e ? scs[20 + i].x : 1.f, s = e ? scs[20 + i].y : 0.f;
        const u64 C2 = pk(c, c), S2 = pk(s, s), N2 = pk(-s, -s);
        const int m = 1 << i;
#pragma unroll
        for (int j = 0; j < 16; j++)
            if (!(j & m)) {
                u64 b0 = A[j], b1 = A[j | m];
                A[j]     = f2fma(S2, b1, f2mul(C2, b0));
                A[j | m] = f2fma(N2, b0, f2mul(C2, b1));
            }
    }
    // CRX2(i, ((i+1)&3)+4): local ctrl -> lane target
#pragma unroll
    for (int i = 0; i < 4; i++) {
        const float c = scs[24 + i].x, s = scs[24 + i].y;
        const u64 C2 = pk(c, c), S2 = pk(s, -s);
        const int ml = 1 << ((i + 1) & 3);
#pragma unroll
        for (int j = 0; j < 16; j++)
            if ((j >> i) & 1) {
                float2 h = upk(A[j]);
                float tx = __shfl_xor_sync(FULL, h.x, ml);
                float ty = __shfl_xor_sync(FULL, h.y, ml);
                A[j] = f2fma(S2, pk(ty, tx), f2mul(C2, A[j]));
            }
    }
    // CRX2(4+i, (i+1)&3): lane ctrl -> local target (real rotation, packed)
#pragma unroll
    for (int i = 0; i < 4; i++) {
        const bool e = (lg >> i) & 1;
        const float c = e ? scs[28 + i].x : 1.f, s = e ? scs[28 + i].y : 0.f;
        const u64 C2 = pk(c, c), S2 = pk(s, s), N2 = pk(-s, -s);
        const int m = 1 << ((i + 1) & 3);
#pragma unroll
        for (int j = 0; j < 16; j++)
            if (!(j & m)) {
                u64 b0 = A[j], b1 = A[j | m];
                A[j]     = f2fma(S2, b1, f2mul(C2, b0));
                A[j | m] = f2fma(N2, b0, f2mul(C2, b1));
            }
    }
    // all 4 CNOT(i,4+i): one dynamic-src shuffle stage (sigma rides along: j fixed)
#pragma unroll
    for (int j = 0; j < 16; j++) {
        float2 h = upk(A[j]);
        int src = gbase | (lg ^ j);
        h.x = __shfl_sync(FULL, h.x, src);
        h.y = __shfl_sync(FULL, h.y, src);
        A[j] = pk(h.x, h.y);
    }
    // all 4 CNOT(4+i,i): FREE via basis relabel (slot j holds basis j^lg).

    // ---- measurement with folded final rot, b-rep corrected:
    // P_a = i*P_b  =>  R_a = -I_b, I_a = R_b.
    float cc0[4], ss0[4];
    {
        float2 aa[16];
        float nj[16];
#pragma unroll
        for (int j = 0; j < 16; j++) {
            aa[j] = upk(A[j]);
            nj[j] = aa[j].x * aa[j].x + aa[j].y * aa[j].y;
        }

        float acc[8];
#pragma unroll
        for (int w = 0; w < 4; w++) {
            const int m = 1 << w;
            const float4 zm = szm[w];
            const float2 nn = sn[w];
            const float sgn = ((lg >> w) & 1) ? -1.f : 1.f;
            const float zmD = zm.x * sgn, zmR = 2.f * zm.y, zmI = 2.f * zm.z * sgn;
            const float xmD = zm.w * sgn, xmR = 2.f * nn.x, xmI = 2.f * nn.y * sgn;
            float z = 0.f, x = 0.f;
#pragma unroll
            for (int j = 0; j < 16; j++) {
                if (j & m) continue;
                float2 e0 = aa[j], e1 = aa[j | m];
                float D = nj[j] - nj[j | m];
                float Rb = e0.x * e1.x + e0.y * e1.y;
                float Ib = e0.x * e1.y - e0.y * e1.x;
                z += zmD * D - zmR * Ib - zmI * Rb;
                x += xmD * D - xmR * Ib - xmI * Rb;
            }
            acc[w] = z;
            acc[4 + w] = x;
        }
        float S = segred8(acc, lg);
        float other = __shfl_xor_sync(FULL, S, 8);
        float amp = sqrtf(S * S + other * other);
        float ang = tanhf(amp) * sgates[wsel];
        float ss_l, cc_l;
        __sincosf(0.5f * ang, &ss_l, &cc_l);
#pragma unroll
        for (int i = 0; i < 4; i++) {
            cc0[i] = __shfl_sync(FULL, cc_l, gbase | (2 * i));
            ss0[i] = __shfl_sync(FULL, ss_l, gbase | (2 * i));
        }
    }

    // ---- value tail: amp-RX fused pairwise (a-rep, unchanged) ----
    {
        {   // wires 0,1 (masks 1,2)
            float AB = cc0[0] * cc0[1], AsB = cc0[0] * ss0[1],
                  sAB = ss0[0] * cc0[1], ss = ss0[0] * ss0[1];
            float2 t0 = shfl2x(vv, 1), t1 = shfl2x(vv, 2), t2 = shfl2x(vv, 3);
            vv = make_float2(AB * vv.x + sAB * t0.y + AsB * t1.y - ss * t2.x,
                             AB * vv.y - sAB * t0.x - AsB * t1.x - ss * t2.y);
        }
        {   // wires 2,3 (masks 4,8)
            float AB = cc0[2] * cc0[3], AsB = cc0[2] * ss0[3],
                  sAB = ss0[2] * cc0[3], ss = ss0[2] * ss0[3];
            float2 t0 = shfl2x(vv, 4), t1 = shfl2x(vv, 8), t2 = shfl2x(vv, 12);
            vv = make_float2(AB * vv.x + sAB * t0.y + AsB * t1.y - ss * t2.x,
                             AB * vv.y - sAB * t0.x - AsB * t1.x - ss * t2.y);
        }
    }
    // CNOT ring folded into measurement via basis permutation pi
    int pi = lg;
    pi ^= (pi & 1) << 1;
    pi ^= ((pi >> 1) & 1) << 2;
    pi ^= ((pi >> 2) & 1) << 3;
    pi ^= (pi >> 3) & 1;

    // ---- final measurement: segmented reduce + direct scatter store ----
    {
        float ov[8];
        const float nv = vv.x * vv.x + vv.y * vv.y;
#pragma unroll
        for (int w = 0; w < 4; w++) ov[w] = ((pi >> w) & 1) ? -nv : nv;
#pragma unroll
        for (int w = 0; w < 4; w++) {
            int r = pi ^ (1 << w);
            r ^= (r >> 3) & 1;
            r ^= ((r >> 2) & 1) << 3;
            r ^= ((r >> 1) & 1) << 2;
            r ^= (r & 1) << 1;
            float tx = __shfl_sync(FULL, vv.x, gbase | r);
            float ty = __shfl_sync(FULL, vv.y, gbase | r);
            ov[4 + w] = vv.x * tx + vv.y * ty;
        }
        float oS = segred8(ov, lg);
        const int oidx = ((lg >> 3) & 1) * 4 + wsel;
        if (!(lg & 1) && item < B)
            out[(long)item * 8 + oidx] = oS;
    }
}

// ---------------------------------------------------------------------------

extern "C" void kernel_launch(void* const* d_in, const int* in_sizes, int n_in,
                              void* d_out, int out_size) {
    const float* x_text  = (const float*)d_in[0];
    const float* x_image = (const float*)d_in[1];
    const float* W_text  = (const float*)d_in[2];
    const float* b_text  = (const float*)d_in[3];
    const float* W_image = (const float*)d_in[4];
    const float* b_image = (const float*)d_in[5];
    const float* q_rot   = (const float*)d_in[6];
    const float* q_crx   = (const float*)d_in[7];
    const float* k_rot   = (const float*)d_in[8];
    const float* k_crx   = (const float*)d_in[9];
    const float* v_rot   = (const float*)d_in[10];
    const float* v_crx   = (const float*)d_in[11];
    const float* c_rot   = (const float*)d_in[12];
    const float* c_crx   = (const float*)d_in[13];
    const float* c_crx2  = (const float*)d_in[14];
    const float* gates   = (const float*)d_in[15];

    int IN = in_sizes[2] / 4;   // W_text is [4, IN]
    int B  = in_sizes[0] / IN;  // x_text is [B, IN]

    int nwarps = (B + 1) / 2;   // 2 items per warp
    int threads = 64;
    int blocks = (nwarps * 32 + threads - 1) / threads;
    qa_fused<<<blocks, threads>>>(x_text, x_image, W_text, b_text, W_image, b_image,
                                  q_rot, q_crx, k_rot, k_crx, v_rot, v_crx,
                                  c_rot, c_crx, c_crx2, gates,
                                  (float*)d_out, B, IN);
}